// round 2
// baseline (speedup 1.0000x reference)
#include <cuda_runtime.h>
#include <math.h>

// Causal attention: S=2048, B=1, H=24, D=128, fp32.
// Inputs [S,B,H,D] (B=1 -> contiguous [S,H,D]); output [B,S,H*D] same layout.
#define S_LEN 2048
#define H_NUM 24
#define D_DIM 128
#define ROWSTRIDE (H_NUM * D_DIM)   // 3072 floats between consecutive s
#define BM 64
#define BN 64
#define QSTRIDE 129                  // smem row stride (pad for bank-conflict-free reads)
#define PSTRIDE 65
#define NTHREADS 256

__global__ __launch_bounds__(NTHREADS, 1)
void attn_fwd(const float* __restrict__ Qg, const float* __restrict__ Kg,
              const float* __restrict__ Vg, float* __restrict__ Og) {
    extern __shared__ float smem[];
    float* sQ = smem;                       // [BM][QSTRIDE]
    float* sK = sQ + BM * QSTRIDE;          // [BN][QSTRIDE]
    float* sV = sK + BN * QSTRIDE;          // [BN][QSTRIDE]
    float* sP = sV + BN * QSTRIDE;          // [BM][PSTRIDE]

    const int qb = blockIdx.x;
    const int h  = blockIdx.y;
    const int q0 = qb * BM;
    const int tid = threadIdx.x;
    const int tx = tid & 15;   // 16 threads across columns
    const int ty = tid >> 4;   // 16 thread-rows, each owns 4 query rows

    const float scale = 0.08838834764831845f;  // 1/sqrt(128)

    // ---- Load Q tile [BM x 128] (float4 gmem loads, scalar smem stores) ----
    {
        const float* qbase = Qg + (size_t)q0 * ROWSTRIDE + h * D_DIM;
        #pragma unroll
        for (int it = 0; it < (BM * (D_DIM / 4)) / NTHREADS; ++it) {
            int idx = tid + it * NTHREADS;   // float4 index within tile
            int r   = idx >> 5;              // 32 float4 per row
            int c4  = idx & 31;
            float4 v = *(const float4*)(qbase + (size_t)r * ROWSTRIDE + c4 * 4);
            float* dst = sQ + r * QSTRIDE + c4 * 4;
            dst[0] = v.x; dst[1] = v.y; dst[2] = v.z; dst[3] = v.w;
        }
    }

    float acc[4][8];
    #pragma unroll
    for (int i = 0; i < 4; ++i)
        #pragma unroll
        for (int j = 0; j < 8; ++j) acc[i][j] = 0.f;
    float m_i[4], l_i[4];
    #pragma unroll
    for (int i = 0; i < 4; ++i) { m_i[i] = -1e30f; l_i[i] = 0.f; }

    const int nkb = qb + 1;  // causal: only k-blocks <= q-block
    for (int kb = 0; kb < nkb; ++kb) {
        __syncthreads();  // previous PV done -> safe to overwrite sK/sV/sP

        // ---- Load K,V tiles [BN x 128] ----
        {
            const int k0 = kb * BN;
            const float* kbase = Kg + (size_t)k0 * ROWSTRIDE + h * D_DIM;
            const float* vbase = Vg + (size_t)k0 * ROWSTRIDE + h * D_DIM;
            #pragma unroll
            for (int it = 0; it < (BN * (D_DIM / 4)) / NTHREADS; ++it) {
                int idx = tid + it * NTHREADS;
                int r   = idx >> 5;
                int c4  = idx & 31;
                float4 kv = *(const float4*)(kbase + (size_t)r * ROWSTRIDE + c4 * 4);
                float4 vv = *(const float4*)(vbase + (size_t)r * ROWSTRIDE + c4 * 4);
                float* kd = sK + r * QSTRIDE + c4 * 4;
                float* vd = sV + r * QSTRIDE + c4 * 4;
                kd[0] = kv.x; kd[1] = kv.y; kd[2] = kv.z; kd[3] = kv.w;
                vd[0] = vv.x; vd[1] = vv.y; vd[2] = vv.z; vd[3] = vv.w;
            }
        }
        __syncthreads();

        // ---- Scores: S[r][c] = sum_d Q[r][d] * K[c][d] ----
        // thread owns rows ty*4+i (i<4), cols tx+16*j (j<4)
        float s[4][4];
        #pragma unroll
        for (int i = 0; i < 4; ++i)
            #pragma unroll
            for (int j = 0; j < 4; ++j) s[i][j] = 0.f;

        #pragma unroll 4
        for (int d = 0; d < D_DIM; ++d) {
            float qv[4], kv[4];
            #pragma unroll
            for (int i = 0; i < 4; ++i) qv[i] = sQ[(ty * 4 + i) * QSTRIDE + d];
            #pragma unroll
            for (int j = 0; j < 4; ++j) kv[j] = sK[(tx + 16 * j) * QSTRIDE + d];
            #pragma unroll
            for (int i = 0; i < 4; ++i)
                #pragma unroll
                for (int j = 0; j < 4; ++j) s[i][j] = fmaf(qv[i], kv[j], s[i][j]);
        }

        // ---- scale + causal mask (only diagonal block needs masking) ----
        const int k0 = kb * BN;
        if (kb == qb) {
            #pragma unroll
            for (int i = 0; i < 4; ++i) {
                int qi = q0 + ty * 4 + i;
                #pragma unroll
                for (int j = 0; j < 4; ++j) {
                    int ki = k0 + tx + 16 * j;
                    s[i][j] = (ki > qi) ? -1e30f : s[i][j] * scale;
                }
            }
        } else {
            #pragma unroll
            for (int i = 0; i < 4; ++i)
                #pragma unroll
                for (int j = 0; j < 4; ++j) s[i][j] *= scale;
        }

        // ---- online softmax (row reductions across 16 tx lanes, in-warp) ----
        #pragma unroll
        for (int i = 0; i < 4; ++i) {
            float mx = fmaxf(fmaxf(s[i][0], s[i][1]), fmaxf(s[i][2], s[i][3]));
            #pragma unroll
            for (int o = 8; o >= 1; o >>= 1)
                mx = fmaxf(mx, __shfl_xor_sync(0xffffffffu, mx, o));
            float m_new = fmaxf(m_i[i], mx);
            float corr  = __expf(m_i[i] - m_new);
            m_i[i] = m_new;

            float rs = 0.f;
            #pragma unroll
            for (int j = 0; j < 4; ++j) {
                float p = __expf(s[i][j] - m_new);
                s[i][j] = p;
                rs += p;
            }
            #pragma unroll
            for (int o = 8; o >= 1; o >>= 1)
                rs += __shfl_xor_sync(0xffffffffu, rs, o);
            l_i[i] = l_i[i] * corr + rs;

            #pragma unroll
            for (int j = 0; j < 8; ++j) acc[i][j] *= corr;
            #pragma unroll
            for (int j = 0; j < 4; ++j)
                sP[(ty * 4 + i) * PSTRIDE + tx + 16 * j] = s[i][j];
        }
        __syncthreads();  // sP ready for all threads

        // ---- PV: acc[r][c] += sum_t P[r][t] * V[t][c] ----
        // thread owns rows ty*4+i, cols tx+16*j (j<8)
        #pragma unroll 4
        for (int t = 0; t < BN; ++t) {
            float pv[4], vv[8];
            #pragma unroll
            for (int i = 0; i < 4; ++i) pv[i] = sP[(ty * 4 + i) * PSTRIDE + t];
            #pragma unroll
            for (int j = 0; j < 8; ++j) vv[j] = sV[t * QSTRIDE + tx + 16 * j];
            #pragma unroll
            for (int i = 0; i < 4; ++i)
                #pragma unroll
                for (int j = 0; j < 8; ++j) acc[i][j] = fmaf(pv[i], vv[j], acc[i][j]);
        }
    }

    // ---- epilogue: normalize and store ----
    #pragma unroll
    for (int i = 0; i < 4; ++i) {
        float inv = 1.f / l_i[i];
        int r = q0 + ty * 4 + i;
        float* orow = Og + (size_t)r * ROWSTRIDE + h * D_DIM;
        #pragma unroll
        for (int j = 0; j < 8; ++j)
            orow[tx + 16 * j] = acc[i][j] * inv;
    }
}

extern "C" void kernel_launch(void* const* d_in, const int* in_sizes, int n_in,
                              void* d_out, int out_size) {
    const float* Q = (const float*)d_in[0];
    const float* K = (const float*)d_in[1];
    const float* V = (const float*)d_in[2];
    float* O = (float*)d_out;

    const size_t smem_bytes =
        (size_t)(BM * QSTRIDE + 2 * BN * QSTRIDE + BM * PSTRIDE) * sizeof(float);  // 115712 B

    cudaFuncSetAttribute(attn_fwd, cudaFuncAttributeMaxDynamicSharedMemorySize,
                         (int)smem_bytes);

    dim3 grid(S_LEN / BM, H_NUM);
    attn_fwd<<<grid, NTHREADS, smem_bytes>>>(Q, K, V, O);
}

// round 3
// speedup vs baseline: 3.5674x; 3.5674x over previous
#include <cuda_runtime.h>

// Causal attention: S=2048, B=1, H=24, D=128, fp32 in/out, TF32 tensor-core compute.
// Inputs [S,B,H,D] (B=1 -> contiguous [S,H,D]); output [B,S,H*D] same layout.
#define S_LEN 2048
#define H_NUM 24
#define D_DIM 128
#define ROWSTRIDE (H_NUM * D_DIM)   // 3072 floats between consecutive tokens
#define BM 128                       // q rows per CTA (16 per warp, 8 warps)
#define BN 64                        // k tokens per iteration
#define QS 132                       // sQ/sK row stride (==4 mod 32: frag loads conflict-free)
#define VS 136                       // sV row stride (==8 mod 32: V b-frag conflict-free)
#define PS 68                        // sP row stride (==4 mod 32)
#define NTH 256

__device__ __forceinline__ unsigned f2tf(float x) {
    unsigned r;
    asm("cvt.rna.tf32.f32 %0, %1;" : "=r"(r) : "f"(x));
    return r;
}

__device__ __forceinline__ void mma8(float c[4], unsigned a0, unsigned a1,
                                     unsigned a2, unsigned a3,
                                     unsigned b0, unsigned b1) {
    asm volatile(
        "mma.sync.aligned.m16n8k8.row.col.f32.tf32.tf32.f32 "
        "{%0,%1,%2,%3},{%4,%5,%6,%7},{%8,%9},{%0,%1,%2,%3};"
        : "+f"(c[0]), "+f"(c[1]), "+f"(c[2]), "+f"(c[3])
        : "r"(a0), "r"(a1), "r"(a2), "r"(a3), "r"(b0), "r"(b1));
}

__global__ __launch_bounds__(NTH, 1)
void attn_fwd(const float* __restrict__ Qg, const float* __restrict__ Kg,
              const float* __restrict__ Vg, float* __restrict__ Og) {
    extern __shared__ float smem[];
    float* sQ = smem;                 // [BM][QS]
    float* sK = sQ + BM * QS;         // [BN][QS]
    float* sV = sK + BN * QS;         // [BN][VS]
    float* sP = sV + BN * VS;         // [BM][PS]

    const int qb = gridDim.x - 1 - blockIdx.x;   // heavy blocks first
    const int h  = blockIdx.y;
    const int q0 = qb * BM;
    const int tid  = threadIdx.x;
    const int lane = tid & 31;
    const int w    = tid >> 5;        // warp id 0..7
    const int la   = lane & 3;        // lane % 4
    const int lb   = lane >> 2;       // lane / 4

    const float scale = 0.08838834764831845f;  // 1/sqrt(128)

    // ---- Load Q tile [BM x 128], pre-scaled, tf32-rounded ----
    {
        const float* qbase = Qg + (size_t)q0 * ROWSTRIDE + h * D_DIM;
        #pragma unroll
        for (int it = 0; it < (BM * 32) / NTH; ++it) {   // 16 float4 per thread
            int idx = tid + it * NTH;
            int r = idx >> 5, c4 = idx & 31;
            float4 v = *(const float4*)(qbase + (size_t)r * ROWSTRIDE + c4 * 4);
            v.x = __uint_as_float(f2tf(v.x * scale));
            v.y = __uint_as_float(f2tf(v.y * scale));
            v.z = __uint_as_float(f2tf(v.z * scale));
            v.w = __uint_as_float(f2tf(v.w * scale));
            *(float4*)(sQ + r * QS + c4 * 4) = v;
        }
    }

    // Per-thread state: O accumulator frags [16 col-tiles][4], scores [8][4]
    float o[16][4];
    #pragma unroll
    for (int t = 0; t < 16; ++t)
        #pragma unroll
        for (int j = 0; j < 4; ++j) o[t][j] = 0.f;
    float m0 = -1e30f, m1 = -1e30f, l0 = 0.f, l1 = 0.f;

    float* sPw = sP + w * 16 * PS;       // warp-private P rows
    const float* sQw = sQ + w * 16 * QS;

    const int nkb = 2 * qb + 2;          // causal: k-blocks covering cols <= q0+BM-1
    for (int kb = 0; kb < nkb; ++kb) {
        __syncthreads();   // previous iteration's PV reads of sK/sV complete

        // ---- Load K,V tiles [BN x 128] (tf32-rounded) ----
        {
            const int k0g = kb * BN;
            const float* kbase = Kg + (size_t)k0g * ROWSTRIDE + h * D_DIM;
            const float* vbase = Vg + (size_t)k0g * ROWSTRIDE + h * D_DIM;
            #pragma unroll
            for (int it = 0; it < (BN * 32) / NTH; ++it) {   // 8 iters
                int idx = tid + it * NTH;
                int r = idx >> 5, c4 = idx & 31;
                float4 kv = *(const float4*)(kbase + (size_t)r * ROWSTRIDE + c4 * 4);
                float4 vv = *(const float4*)(vbase + (size_t)r * ROWSTRIDE + c4 * 4);
                kv.x = __uint_as_float(f2tf(kv.x));
                kv.y = __uint_as_float(f2tf(kv.y));
                kv.z = __uint_as_float(f2tf(kv.z));
                kv.w = __uint_as_float(f2tf(kv.w));
                vv.x = __uint_as_float(f2tf(vv.x));
                vv.y = __uint_as_float(f2tf(vv.y));
                vv.z = __uint_as_float(f2tf(vv.z));
                vv.w = __uint_as_float(f2tf(vv.w));
                *(float4*)(sK + r * QS + c4 * 4) = kv;
                *(float4*)(sV + r * VS + c4 * 4) = vv;
            }
        }
        __syncthreads();

        // ---- S = Q K^T via tf32 mma: warp computes [16 x 64] ----
        float sc[8][4];
        #pragma unroll
        for (int n = 0; n < 8; ++n)
            #pragma unroll
            for (int j = 0; j < 4; ++j) sc[n][j] = 0.f;

        #pragma unroll
        for (int kk = 0; kk < 16; ++kk) {
            const int k0 = kk * 8;
            unsigned a0 = __float_as_uint(sQw[lb * QS + k0 + la]);
            unsigned a1 = __float_as_uint(sQw[(lb + 8) * QS + k0 + la]);
            unsigned a2 = __float_as_uint(sQw[lb * QS + k0 + la + 4]);
            unsigned a3 = __float_as_uint(sQw[(lb + 8) * QS + k0 + la + 4]);
            #pragma unroll
            for (int n = 0; n < 8; ++n) {
                unsigned b0 = __float_as_uint(sK[(n * 8 + lb) * QS + k0 + la]);
                unsigned b1 = __float_as_uint(sK[(n * 8 + lb) * QS + k0 + la + 4]);
                mma8(sc[n], a0, a1, a2, a3, b0, b1);
            }
        }

        // ---- causal mask (only the last two k-blocks intersect diagonal) ----
        const int row_lo = q0 + w * 16 + lb;
        if (kb * BN >= q0) {
            #pragma unroll
            for (int n = 0; n < 8; ++n) {
                const int col = kb * BN + n * 8 + 2 * la;
                if (col     > row_lo)     sc[n][0] = -1e30f;
                if (col + 1 > row_lo)     sc[n][1] = -1e30f;
                if (col     > row_lo + 8) sc[n][2] = -1e30f;
                if (col + 1 > row_lo + 8) sc[n][3] = -1e30f;
            }
        }

        // ---- online softmax (rows lo/hi; reduce over la-group of 4 lanes) ----
        float mx0 = -1e30f, mx1 = -1e30f;
        #pragma unroll
        for (int n = 0; n < 8; ++n) {
            mx0 = fmaxf(mx0, fmaxf(sc[n][0], sc[n][1]));
            mx1 = fmaxf(mx1, fmaxf(sc[n][2], sc[n][3]));
        }
        mx0 = fmaxf(mx0, __shfl_xor_sync(0xffffffffu, mx0, 1));
        mx0 = fmaxf(mx0, __shfl_xor_sync(0xffffffffu, mx0, 2));
        mx1 = fmaxf(mx1, __shfl_xor_sync(0xffffffffu, mx1, 1));
        mx1 = fmaxf(mx1, __shfl_xor_sync(0xffffffffu, mx1, 2));

        const float mn0 = fmaxf(m0, mx0);
        const float mn1 = fmaxf(m1, mx1);
        const float corr0 = __expf(m0 - mn0);
        const float corr1 = __expf(m1 - mn1);
        m0 = mn0; m1 = mn1;

        float rs0 = 0.f, rs1 = 0.f;
        #pragma unroll
        for (int n = 0; n < 8; ++n) {
            float p0 = __expf(sc[n][0] - mn0);
            float p1 = __expf(sc[n][1] - mn0);
            float p2 = __expf(sc[n][2] - mn1);
            float p3 = __expf(sc[n][3] - mn1);
            rs0 += p0 + p1;
            rs1 += p2 + p3;
            *(float2*)(sPw + lb * PS + n * 8 + 2 * la) =
                make_float2(__uint_as_float(f2tf(p0)), __uint_as_float(f2tf(p1)));
            *(float2*)(sPw + (lb + 8) * PS + n * 8 + 2 * la) =
                make_float2(__uint_as_float(f2tf(p2)), __uint_as_float(f2tf(p3)));
        }
        rs0 += __shfl_xor_sync(0xffffffffu, rs0, 1);
        rs0 += __shfl_xor_sync(0xffffffffu, rs0, 2);
        rs1 += __shfl_xor_sync(0xffffffffu, rs1, 1);
        rs1 += __shfl_xor_sync(0xffffffffu, rs1, 2);
        l0 = l0 * corr0 + rs0;
        l1 = l1 * corr1 + rs1;

        #pragma unroll
        for (int t = 0; t < 16; ++t) {
            o[t][0] *= corr0; o[t][1] *= corr0;
            o[t][2] *= corr1; o[t][3] *= corr1;
        }
        __syncwarp();   // sP visible within warp

        // ---- O += P V via tf32 mma: [16 x 128] ----
        #pragma unroll
        for (int kk = 0; kk < 8; ++kk) {
            const int k0 = kk * 8;
            unsigned a0 = __float_as_uint(sPw[lb * PS + k0 + la]);
            unsigned a1 = __float_as_uint(sPw[(lb + 8) * PS + k0 + la]);
            unsigned a2 = __float_as_uint(sPw[lb * PS + k0 + la + 4]);
            unsigned a3 = __float_as_uint(sPw[(lb + 8) * PS + k0 + la + 4]);
            #pragma unroll
            for (int t = 0; t < 16; ++t) {
                unsigned b0 = __float_as_uint(sV[(k0 + la) * VS + t * 8 + lb]);
                unsigned b1 = __float_as_uint(sV[(k0 + la + 4) * VS + t * 8 + lb]);
                mma8(o[t], a0, a1, a2, a3, b0, b1);
            }
        }
        __syncwarp();   // P reads done before next iteration overwrites sP
    }

    // ---- epilogue: normalize, store ----
    const float inv0 = 1.f / l0;
    const float inv1 = 1.f / l1;
    const int row0 = q0 + w * 16 + lb;
    const int row1 = row0 + 8;
    float* o0 = Og + (size_t)row0 * ROWSTRIDE + h * D_DIM;
    float* o1 = Og + (size_t)row1 * ROWSTRIDE + h * D_DIM;
    #pragma unroll
    for (int t = 0; t < 16; ++t) {
        *(float2*)(o0 + t * 8 + 2 * la) = make_float2(o[t][0] * inv0, o[t][1] * inv0);
        *(float2*)(o1 + t * 8 + 2 * la) = make_float2(o[t][2] * inv1, o[t][3] * inv1);
    }
}

extern "C" void kernel_launch(void* const* d_in, const int* in_sizes, int n_in,
                              void* d_out, int out_size) {
    const float* Q = (const float*)d_in[0];
    const float* K = (const float*)d_in[1];
    const float* V = (const float*)d_in[2];
    float* O = (float*)d_out;

    const size_t smem_bytes =
        (size_t)(BM * QS + BN * QS + BN * VS + BM * PS) * sizeof(float);  // 171008 B

    cudaFuncSetAttribute(attn_fwd, cudaFuncAttributeMaxDynamicSharedMemorySize,
                         (int)smem_bytes);

    dim3 grid(S_LEN / BM, H_NUM);
    attn_fwd<<<grid, NTH, smem_bytes>>>(Q, K, V, O);
}